// round 1
// baseline (speedup 1.0000x reference)
#include <cuda_runtime.h>
#include <cuda_bf16.h>
#include <cstdint>

#define B_ROWS 16384
#define DDIM   1024
#define CCLS   1000
#define CPAD   1024

#define BM 64
#define BN 128
#define BK 32
#define AS_STRIDE 1032   // elems (padded: conflict-free ldS for A frags)
#define BS_STRIDE 40     // elems (padded: conflict-free ldS for B frags)

// Scratch (static device globals — allocation-free rule)
__device__ __nv_bfloat16 g_x[(size_t)B_ROWS * DDIM];   // 32 MB normalized bf16 x
__device__ __nv_bfloat16 g_p[(size_t)CPAD * DDIM];     // 2 MB bf16 prototypes (zero-padded rows 1000..1023)

// ---------------------------------------------------------------------------
// Kernel 0: zero output scalar
// ---------------------------------------------------------------------------
__global__ void zero_out(float* out) { out[0] = 0.0f; }

// ---------------------------------------------------------------------------
// Kernel 1: per-row L2 normalize hidden_states, write bf16
// ---------------------------------------------------------------------------
__global__ __launch_bounds__(256) void norm_kernel(const float* __restrict__ hs) {
    int row = blockIdx.x;
    const float4* src = (const float4*)(hs + (size_t)row * DDIM);
    float4 v = src[threadIdx.x];
    float ss = v.x * v.x + v.y * v.y + v.z * v.z + v.w * v.w;
    #pragma unroll
    for (int o = 16; o; o >>= 1) ss += __shfl_xor_sync(0xffffffffu, ss, o);
    __shared__ float wsum[8];
    int w = threadIdx.x >> 5, l = threadIdx.x & 31;
    if (l == 0) wsum[w] = ss;
    __syncthreads();
    float tot = 0.f;
    #pragma unroll
    for (int i = 0; i < 8; i++) tot += wsum[i];
    float s = rsqrtf(tot);
    __nv_bfloat162* dst = (__nv_bfloat162*)(g_x + (size_t)row * DDIM + threadIdx.x * 4);
    dst[0] = __floats2bfloat162_rn(v.x * s, v.y * s);
    dst[1] = __floats2bfloat162_rn(v.z * s, v.w * s);
}

// ---------------------------------------------------------------------------
// Kernel 2: convert prototypes to bf16, zero-pad rows [1000, 1024)
// ---------------------------------------------------------------------------
__global__ __launch_bounds__(256) void convp(const float* __restrict__ P) {
    int i = blockIdx.x * 256 + threadIdx.x;   // over CPAD*DDIM
    int row = i >> 10;
    int col = i & 1023;
    float v = (row < CCLS) ? P[(size_t)row * DDIM + col] : 0.f;
    g_p[i] = __float2bfloat16(v);
}

// ---------------------------------------------------------------------------
// Kernel 3: fused GEMM (bf16 mma.sync) + sum-exp + CE loss
// ---------------------------------------------------------------------------
__device__ __forceinline__ void cpa16(void* dst, const void* src) {
    uint32_t d = (uint32_t)__cvta_generic_to_shared(dst);
    asm volatile("cp.async.cg.shared.global [%0], [%1], 16;\n" :: "r"(d), "l"(src));
}

__device__ __forceinline__ void mma16816(float* c, const uint32_t* a, uint32_t b0, uint32_t b1) {
    asm volatile(
        "mma.sync.aligned.m16n8k16.row.col.f32.bf16.bf16.f32 "
        "{%0,%1,%2,%3},{%4,%5,%6,%7},{%8,%9},{%0,%1,%2,%3};\n"
        : "+f"(c[0]), "+f"(c[1]), "+f"(c[2]), "+f"(c[3])
        : "r"(a[0]), "r"(a[1]), "r"(a[2]), "r"(a[3]), "r"(b0), "r"(b1));
}

extern __shared__ char smem_raw[];

#define SMEM_AS_BYTES   (BM * AS_STRIDE * 2)               // 132096
#define SMEM_BS_BYTES   (2 * BN * BS_STRIDE * 2)           // 20480
#define SMEM_BYTES_TOT  (SMEM_AS_BYTES + SMEM_BS_BYTES + (64*4 + 64 + 64 + 64) * 4)

__global__ __launch_bounds__(256, 1) void gemm_ce(const long long* __restrict__ labels,
                                                  float* __restrict__ out) {
    __nv_bfloat16* As = (__nv_bfloat16*)smem_raw;
    __nv_bfloat16* Bs = (__nv_bfloat16*)(smem_raw + SMEM_AS_BYTES);
    float* partial = (float*)(smem_raw + SMEM_AS_BYTES + SMEM_BS_BYTES);  // [64][4]
    float* s_run   = partial + 64 * 4;                                    // [64]
    float* goldsm  = s_run + 64;                                          // [64]
    int*   lab     = (int*)(goldsm + 64);                                 // [64]

    const int tid  = threadIdx.x;
    const int row0 = blockIdx.x * BM;

    // ---- load A tile (full K) into smem, padded stride ----
    {
        const uint4* src = (const uint4*)(g_x + (size_t)row0 * DDIM);
        #pragma unroll
        for (int i = 0; i < (BM * DDIM / 8) / 256; i++) {
            int c = tid + i * 256;
            int r = c >> 7;                 // 128 uint4 per row
            int col8 = (c & 127) * 8;
            uint4 v = src[c];
            *(uint4*)&As[r * AS_STRIDE + col8] = v;
        }
    }
    if (tid < 64) {
        lab[tid]    = (int)labels[row0 + tid];
        s_run[tid]  = 0.f;
        goldsm[tid] = 0.f;
    }
    __syncthreads();

    const int lane = tid & 31, warp = tid >> 5;
    const int warpM = warp >> 2, warpN = warp & 3;
    const int g = lane >> 2, q = lane & 3;
    const uint32_t* As32 = (const uint32_t*)As;
    const uint32_t* Bs32 = (const uint32_t*)Bs;

    for (int chunk = 0; chunk < 8; chunk++) {
        const int n0 = chunk * BN;
        float acc[2][4][4];
        #pragma unroll
        for (int mt = 0; mt < 2; mt++)
            #pragma unroll
            for (int nt = 0; nt < 4; nt++)
                #pragma unroll
                for (int j = 0; j < 4; j++) acc[mt][nt][j] = 0.f;

        // prologue fill buffer 0
        {
            #pragma unroll
            for (int i = 0; i < 2; i++) {
                int c = tid + i * 256;
                int r = c >> 2, seg = c & 3;
                cpa16(&Bs[0 * BN * BS_STRIDE + r * BS_STRIDE + seg * 8],
                      g_p + (size_t)(n0 + r) * DDIM + 0 + seg * 8);
            }
            asm volatile("cp.async.commit_group;\n");
        }

        for (int t = 0; t < 32; t++) {
            const int kk = t * BK;
            if (t + 1 < 32) {
                int buf = (t + 1) & 1;
                #pragma unroll
                for (int i = 0; i < 2; i++) {
                    int c = tid + i * 256;
                    int r = c >> 2, seg = c & 3;
                    cpa16(&Bs[buf * BN * BS_STRIDE + r * BS_STRIDE + seg * 8],
                          g_p + (size_t)(n0 + r) * DDIM + (kk + BK) + seg * 8);
                }
                asm volatile("cp.async.commit_group;\n");
                asm volatile("cp.async.wait_group 1;\n" ::: "memory");
            } else {
                asm volatile("cp.async.wait_group 0;\n" ::: "memory");
            }
            __syncthreads();

            const uint32_t* Bp = Bs32 + (t & 1) * (BN * BS_STRIDE / 2);
            #pragma unroll
            for (int ks = 0; ks < 2; ks++) {
                const int koff = kk + ks * 16;
                uint32_t a[2][4];
                #pragma unroll
                for (int mt = 0; mt < 2; mt++) {
                    int r = warpM * 32 + mt * 16 + g;
                    uint32_t i0 = r * (AS_STRIDE / 2) + (koff >> 1) + q;
                    a[mt][0] = As32[i0];
                    a[mt][1] = As32[i0 + 8 * (AS_STRIDE / 2)];
                    a[mt][2] = As32[i0 + 4];
                    a[mt][3] = As32[i0 + 8 * (AS_STRIDE / 2) + 4];
                }
                #pragma unroll
                for (int nt = 0; nt < 4; nt++) {
                    int n = warpN * 32 + nt * 8 + g;
                    uint32_t j0 = n * (BS_STRIDE / 2) + ks * 8 + q;
                    uint32_t b0 = Bp[j0], b1 = Bp[j0 + 4];
                    mma16816(acc[0][nt], a[0], b0, b1);
                    mma16816(acc[1][nt], a[1], b0, b1);
                }
            }
            __syncthreads();
        }

        // ---- per-chunk sum-exp + gold capture ----
        #pragma unroll
        for (int mt = 0; mt < 2; mt++) {
            #pragma unroll
            for (int rh = 0; rh < 2; rh++) {
                int rloc = warpM * 32 + mt * 16 + rh * 8 + g;
                int labr = lab[rloc];
                float se = 0.f;
                #pragma unroll
                for (int nt = 0; nt < 4; nt++) {
                    int c0 = n0 + warpN * 32 + nt * 8 + q * 2;
                    float v0 = acc[mt][nt][rh * 2 + 0];
                    float v1 = acc[mt][nt][rh * 2 + 1];
                    if (c0     < CCLS) se += __expf(v0);
                    if (c0 + 1 < CCLS) se += __expf(v1);
                    if (c0     == labr) goldsm[rloc] = v0;
                    if (c0 + 1 == labr) goldsm[rloc] = v1;
                }
                se += __shfl_xor_sync(0xffffffffu, se, 1);
                se += __shfl_xor_sync(0xffffffffu, se, 2);
                if (q == 0) partial[rloc * 4 + warpN] = se;
            }
        }
        __syncthreads();
        if (tid < 64) {
            s_run[tid] += partial[tid * 4] + partial[tid * 4 + 1]
                        + partial[tid * 4 + 2] + partial[tid * 4 + 3];
        }
        __syncthreads();
    }

    if (tid < 64) {
        float loss = __logf(s_run[tid]) - goldsm[tid];
        atomicAdd(out, loss * (1.0f / (float)B_ROWS));
    }
}

// ---------------------------------------------------------------------------
extern "C" void kernel_launch(void* const* d_in, const int* in_sizes, int n_in,
                              void* d_out, int out_size) {
    const float*     hs = (const float*)d_in[0];       // [16384,1024] f32
    const float*     pm = (const float*)d_in[1];       // [1000,1024]  f32
    const long long* lb = (const long long*)d_in[2];   // [16384]      i64
    float* out = (float*)d_out;

    cudaFuncSetAttribute(gemm_ce, cudaFuncAttributeMaxDynamicSharedMemorySize, SMEM_BYTES_TOT);

    zero_out<<<1, 1>>>(out);
    norm_kernel<<<B_ROWS, 256>>>(hs);
    convp<<<(CPAD * DDIM) / 256, 256>>>(pm);
    gemm_ce<<<B_ROWS / BM, 256, SMEM_BYTES_TOT>>>(lb, out);
}

// round 3
// speedup vs baseline: 1.1040x; 1.1040x over previous
#include <cuda_runtime.h>
#include <cuda_bf16.h>
#include <cstdint>

#define B_ROWS 16384
#define DDIM   1024
#define CCLS   1000

#define BM 64
#define BN 128          // classes per chunk
#define BK 128          // k per B stage
#define NCHUNK 8
#define NITER  64       // 8 chunks * 8 k-iters

#define A_STRIDE_B 2064     // bytes per A row (1032 elems, 129 banks -> conflict-free LDSM)
#define B_STRIDE_B 272      // bytes per B row (136 elems, 17 banks -> conflict-free LDSM)

#define SM_A     0
#define SM_A_SZ  (BM * A_STRIDE_B)            // 132096
#define SM_B     SM_A_SZ
#define SM_BBUF  (BN * B_STRIDE_B)            // 34816
#define SM_MISC  (SM_B + 2 * SM_BBUF)         // 201728
// misc: partial[64][8] f32 (2048) | s_run[64] | gold[64] | lab[64]
#define SMEM_TOTAL (SM_MISC + 2048 + 64*4*3)  // 204544

// Scratch (allocation-free rule)
__device__ __nv_bfloat16 g_x[(size_t)B_ROWS * DDIM];
__device__ __nv_bfloat16 g_p[(size_t)1024 * DDIM];

__device__ __forceinline__ uint32_t smem_u32(const void* p) {
    uint32_t a;
    asm("{ .reg .u64 t; cvta.to.shared.u64 t, %1; cvt.u32.u64 %0, t; }" : "=r"(a) : "l"(p));
    return a;
}
__device__ __forceinline__ void cpa16(uint32_t daddr, const void* src) {
    asm volatile("cp.async.cg.shared.global [%0], [%1], 16;" :: "r"(daddr), "l"(src));
}
__device__ __forceinline__ void ldsm4(uint32_t* r, uint32_t addr) {
    asm volatile("ldmatrix.sync.aligned.m8n8.x4.shared.b16 {%0,%1,%2,%3}, [%4];"
                 : "=r"(r[0]), "=r"(r[1]), "=r"(r[2]), "=r"(r[3]) : "r"(addr));
}
__device__ __forceinline__ void mma16816(float* c, const uint32_t* a, uint32_t b0, uint32_t b1) {
    asm volatile(
        "mma.sync.aligned.m16n8k16.row.col.f32.bf16.bf16.f32 "
        "{%0,%1,%2,%3},{%4,%5,%6,%7},{%8,%9},{%0,%1,%2,%3};\n"
        : "+f"(c[0]), "+f"(c[1]), "+f"(c[2]), "+f"(c[3])
        : "r"(a[0]), "r"(a[1]), "r"(a[2]), "r"(a[3]), "r"(b0), "r"(b1));
}

// ---------------------------------------------------------------------------
__global__ void zero_out(float* out) { out[0] = 0.0f; }

// per-row L2 normalize -> bf16
__global__ __launch_bounds__(256) void norm_kernel(const float* __restrict__ hs) {
    int row = blockIdx.x;
    const float4* src = (const float4*)(hs + (size_t)row * DDIM);
    float4 v = src[threadIdx.x];
    float ss = v.x * v.x + v.y * v.y + v.z * v.z + v.w * v.w;
    #pragma unroll
    for (int o = 16; o; o >>= 1) ss += __shfl_xor_sync(0xffffffffu, ss, o);
    __shared__ float wsum[8];
    int w = threadIdx.x >> 5, l = threadIdx.x & 31;
    if (l == 0) wsum[w] = ss;
    __syncthreads();
    float tot = 0.f;
    #pragma unroll
    for (int i = 0; i < 8; i++) tot += wsum[i];
    float s = rsqrtf(tot);
    __nv_bfloat162* dst = (__nv_bfloat162*)(g_x + (size_t)row * DDIM + threadIdx.x * 4);
    dst[0] = __floats2bfloat162_rn(v.x * s, v.y * s);
    dst[1] = __floats2bfloat162_rn(v.z * s, v.w * s);
}

// prototypes -> bf16, zero-pad rows [1000,1024)
__global__ __launch_bounds__(256) void convp(const float* __restrict__ P) {
    int i = blockIdx.x * 256 + threadIdx.x;
    int row = i >> 10, col = i & 1023;
    float v = (row < CCLS) ? P[(size_t)row * DDIM + col] : 0.f;
    g_p[i] = __float2bfloat16(v);
}

// ---------------------------------------------------------------------------
extern __shared__ char smem_g[];

__device__ __forceinline__ void loadB(uint32_t sb, int g, int tid) {
    // iteration g: chunk = g>>3, k-offset = (g&7)*128, buffer = g&1
    const int chunk = g >> 3;
    const int kk = (g & 7) * BK;
    uint32_t base = sb + SM_B + (g & 1) * SM_BBUF;
    const __nv_bfloat16* src = g_p + (size_t)chunk * BN * DDIM + kk;
    #pragma unroll
    for (int i = 0; i < 4; i++) {
        int idx = tid + i * 512;
        int r = idx >> 4, s = idx & 15;          // 16 x 16B segments per 256B row
        cpa16(base + r * B_STRIDE_B + s * 16, src + (size_t)r * DDIM + s * 8);
    }
}

__global__ __launch_bounds__(512, 1) void gemm_ce(const long long* __restrict__ labels,
                                                  float* __restrict__ out) {
    uint32_t sb = smem_u32(smem_g);
    const int tid = threadIdx.x;
    const int wid = tid >> 5, lane = tid & 31;
    const int row0 = blockIdx.x * BM;

    float* partial = (float*)(smem_g + SM_MISC);       // [64][8]
    float* s_run   = partial + 64 * 8;                 // [64]
    float* goldsm  = s_run + 64;                       // [64]
    int*   labsm   = (int*)(goldsm + 64);              // [64]

    // ---- prologue: A tile (full K) + first B stage ----
    {
        const __nv_bfloat16* asrc = g_x + (size_t)row0 * DDIM;
        #pragma unroll
        for (int i = 0; i < 16; i++) {
            int idx = tid + i * 512;
            int r = idx >> 7, s = idx & 127;     // 128 x 16B per 2048B row
            cpa16(sb + SM_A + r * A_STRIDE_B + s * 16, asrc + (size_t)r * DDIM + s * 8);
        }
        asm volatile("cp.async.commit_group;");
        loadB(sb, 0, tid);
        asm volatile("cp.async.commit_group;");
    }
    if (tid < 64) {
        s_run[tid]  = 0.f;
        goldsm[tid] = 0.f;
        labsm[tid]  = (int)labels[row0 + tid];
    }

    const int warpM = wid >> 3, warpN = wid & 7;  // 2 x 8 warp grid, warp tile 32x16
    // ldmatrix lane addressing
    const int rowA  = warpM * 32 + (lane & 7) + ((lane >> 3) & 1) * 8;
    const int kAp   = (lane >> 4) * 8;
    const uint32_t aAddr0 = sb + SM_A + rowA * A_STRIDE_B + kAp * 2;
    const int rowB  = warpN * 16 + (lane & 7) + (lane >> 4) * 8;
    const int kBp   = ((lane >> 3) & 1) * 8;
    const uint32_t bAddr0 = rowB * B_STRIDE_B + kBp * 2;

    float acc[2][2][4];
    #pragma unroll
    for (int mt = 0; mt < 2; mt++)
        #pragma unroll
        for (int nt = 0; nt < 2; nt++)
            #pragma unroll
            for (int j = 0; j < 4; j++) acc[mt][nt][j] = 0.f;

    for (int it = 0; it < NITER; it++) {
        __syncthreads();   // all warps done reading the buffer we're about to refill
        if (it + 1 < NITER) {
            loadB(sb, it + 1, tid);
            asm volatile("cp.async.commit_group;");
            asm volatile("cp.async.wait_group 1;" ::: "memory");
        } else {
            asm volatile("cp.async.wait_group 0;" ::: "memory");
        }
        __syncthreads();   // current stage visible to all

        const int kk = (it & 7) * BK;
        const uint32_t bBuf = sb + SM_B + (it & 1) * SM_BBUF + bAddr0;
        #pragma unroll
        for (int ks = 0; ks < 8; ks++) {
            uint32_t ra0[4], ra1[4], rb[4];
            ldsm4(ra0, aAddr0 + (kk + ks * 16) * 2);
            ldsm4(ra1, aAddr0 + 16 * A_STRIDE_B + (kk + ks * 16) * 2);
            ldsm4(rb,  bBuf + ks * 32);
            mma16816(acc[0][0], ra0, rb[0], rb[1]);
            mma16816(acc[0][1], ra0, rb[2], rb[3]);
            mma16816(acc[1][0], ra1, rb[0], rb[1]);
            mma16816(acc[1][1], ra1, rb[2], rb[3]);
        }

        if ((it & 7) == 7) {
            // ---- fused epilogue for chunk = it>>3 ----
            const int chunk = it >> 3;
            #pragma unroll
            for (int mt = 0; mt < 2; mt++) {
                #pragma unroll
                for (int rh = 0; rh < 2; rh++) {
                    int rloc = warpM * 32 + mt * 16 + rh * 8 + (lane >> 2);
                    int labr = labsm[rloc];
                    float se = 0.f;
                    #pragma unroll
                    for (int nt = 0; nt < 2; nt++) {
                        int c0 = chunk * BN + warpN * 16 + nt * 8 + (lane & 3) * 2;
                        float v0 = acc[mt][nt][rh * 2 + 0];
                        float v1 = acc[mt][nt][rh * 2 + 1];
                        if (c0     < CCLS) se += __expf(v0);
                        if (c0 + 1 < CCLS) se += __expf(v1);
                        if (c0     == labr) goldsm[rloc] = v0;
                        if (c0 + 1 == labr) goldsm[rloc] = v1;
                    }
                    se += __shfl_xor_sync(0xffffffffu, se, 1);
                    se += __shfl_xor_sync(0xffffffffu, se, 2);
                    if ((lane & 3) == 0) partial[rloc * 8 + warpN] = se;
                }
            }
            __syncthreads();
            if (tid < 64) {
                float t = 0.f;
                #pragma unroll
                for (int i = 0; i < 8; i++) t += partial[tid * 8 + i];
                s_run[tid] += t;
            }
            #pragma unroll
            for (int mt = 0; mt < 2; mt++)
                #pragma unroll
                for (int nt = 0; nt < 2; nt++)
                    #pragma unroll
                    for (int j = 0; j < 4; j++) acc[mt][nt][j] = 0.f;
        }
    }

    __syncthreads();
    if (tid < 64) {
        float loss = __logf(s_run[tid]) - goldsm[tid];
        atomicAdd(out, loss * (1.0f / (float)B_ROWS));
    }
}

// ---------------------------------------------------------------------------
extern "C" void kernel_launch(void* const* d_in, const int* in_sizes, int n_in,
                              void* d_out, int out_size) {
    const float*     hs = (const float*)d_in[0];
    const float*     pm = (const float*)d_in[1];
    const long long* lb = (const long long*)d_in[2];
    float* out = (float*)d_out;

    cudaFuncSetAttribute(gemm_ce, cudaFuncAttributeMaxDynamicSharedMemorySize, SMEM_TOTAL);

    zero_out<<<1, 1>>>(out);
    norm_kernel<<<B_ROWS, 256>>>(hs);
    convp<<<(1024 * DDIM) / 256, 256>>>(pm);
    gemm_ce<<<B_ROWS / BM, 512, SMEM_TOTAL>>>(lb, out);
}

// round 5
// speedup vs baseline: 2.1765x; 1.9714x over previous
#include <cuda_runtime.h>
#include <cuda_bf16.h>
#include <cstdint>

#define B_ROWS 16384
#define DDIM   1024
#define CCLS   1000

#define BM 128
#define BN 128
#define BK 64
#define KITERS 16
#define STAGES 3
#define STAGE_BYTES 32768          // A 16KB + B 16KB
#define SM_MISC (STAGES * STAGE_BYTES)          // 98304
#define SMEM_TOTAL (SM_MISC + 128*4*4 + 128*4)  // + partial[128][4] + labsm[128]

// Scratch (allocation-free rule)
__device__ __nv_bfloat16 g_x[(size_t)B_ROWS * DDIM];
__device__ __nv_bfloat16 g_p[(size_t)1024 * DDIM];
__device__ float g_rowsum[B_ROWS];
__device__ float g_gold[B_ROWS];

__device__ __forceinline__ uint32_t smem_u32(const void* p) {
    uint32_t a;
    asm("{ .reg .u64 t; cvta.to.shared.u64 t, %1; cvt.u32.u64 %0, t; }" : "=r"(a) : "l"(p));
    return a;
}
__device__ __forceinline__ void cpa16(uint32_t daddr, const void* src) {
    asm volatile("cp.async.cg.shared.global [%0], [%1], 16;" :: "r"(daddr), "l"(src));
}
__device__ __forceinline__ void ldsm4(uint32_t* r, uint32_t addr) {
    asm volatile("ldmatrix.sync.aligned.m8n8.x4.shared.b16 {%0,%1,%2,%3}, [%4];"
                 : "=r"(r[0]), "=r"(r[1]), "=r"(r[2]), "=r"(r[3]) : "r"(addr));
}
__device__ __forceinline__ void mma16816(float* c, const uint32_t* a, uint32_t b0, uint32_t b1) {
    asm volatile(
        "mma.sync.aligned.m16n8k16.row.col.f32.bf16.bf16.f32 "
        "{%0,%1,%2,%3},{%4,%5,%6,%7},{%8,%9},{%0,%1,%2,%3};\n"
        : "+f"(c[0]), "+f"(c[1]), "+f"(c[2]), "+f"(c[3])
        : "r"(a[0]), "r"(a[1]), "r"(a[2]), "r"(a[3]), "r"(b0), "r"(b1));
}

// ---------------------------------------------------------------------------
__global__ void zero_out(float* out) { out[0] = 0.0f; }

__global__ __launch_bounds__(256) void norm_kernel(const float* __restrict__ hs) {
    int row = blockIdx.x;
    if (threadIdx.x == 0) g_rowsum[row] = 0.0f;
    const float4* src = (const float4*)(hs + (size_t)row * DDIM);
    float4 v = src[threadIdx.x];
    float ss = v.x * v.x + v.y * v.y + v.z * v.z + v.w * v.w;
    #pragma unroll
    for (int o = 16; o; o >>= 1) ss += __shfl_xor_sync(0xffffffffu, ss, o);
    __shared__ float wsum[8];
    int w = threadIdx.x >> 5, l = threadIdx.x & 31;
    if (l == 0) wsum[w] = ss;
    __syncthreads();
    float tot = 0.f;
    #pragma unroll
    for (int i = 0; i < 8; i++) tot += wsum[i];
    float s = rsqrtf(tot);
    __nv_bfloat162* dst = (__nv_bfloat162*)(g_x + (size_t)row * DDIM + threadIdx.x * 4);
    dst[0] = __floats2bfloat162_rn(v.x * s, v.y * s);
    dst[1] = __floats2bfloat162_rn(v.z * s, v.w * s);
}

__global__ __launch_bounds__(256) void convp(const float* __restrict__ P) {
    int i = blockIdx.x * 256 + threadIdx.x;
    int row = i >> 10, col = i & 1023;
    float v = (row < CCLS) ? P[(size_t)row * DDIM + col] : 0.f;
    g_p[i] = __float2bfloat16(v);
}

// ---------------------------------------------------------------------------
extern __shared__ char smem_g[];

__device__ __forceinline__ void load_stage(uint32_t sb, int stage, int tid,
                                            const __nv_bfloat16* gA,
                                            const __nv_bfloat16* gB) {
    uint32_t base = sb + (stage % STAGES) * STAGE_BYTES;
    const int kk = stage * BK;
    #pragma unroll
    for (int i = 0; i < 4; i++) {
        int idx = tid + i * 256;
        int r = idx >> 3, s = idx & 7;
        uint32_t off = (uint32_t)(r * 128 + ((s ^ (r & 7)) << 4));
        cpa16(base + off,         gA + (size_t)r * DDIM + kk + s * 8);
        cpa16(base + 16384 + off, gB + (size_t)r * DDIM + kk + s * 8);
    }
}

__global__ __launch_bounds__(256, 2) void gemm_ce(const long long* __restrict__ labels) {
    uint32_t sb = smem_u32(smem_g);
    const int tid = threadIdx.x;
    const int wid = tid >> 5, lane = tid & 31;
    const int row0 = blockIdx.x * BM;
    const int n0   = blockIdx.y * BN;

    float* partial = (float*)(smem_g + SM_MISC);   // [128][4]
    int*   labsm   = (int*)(partial + 128 * 4);    // [128]

    const __nv_bfloat16* gA = g_x + (size_t)row0 * DDIM;
    const __nv_bfloat16* gB = g_p + (size_t)n0 * DDIM;

    load_stage(sb, 0, tid, gA, gB);
    asm volatile("cp.async.commit_group;");
    load_stage(sb, 1, tid, gA, gB);
    asm volatile("cp.async.commit_group;");
    if (tid < 128) labsm[tid] = (int)labels[row0 + tid];

    const int warpM = wid >> 2;      // 0..1  (64 rows each)
    const int warpN = wid & 3;       // 0..3  (32 cols each)
    const int x7 = lane & 7;
    // A: 16x16 ldsm tile lane map
    const int laneRowA = (lane & 7) + ((lane >> 3) & 1) * 8;
    const int kHalfA   = lane >> 4;
    // B: 16 rows, k-half from bit3
    const int laneRowB = (lane & 7) + (lane >> 4) * 8;
    const int kHalfB   = (lane >> 3) & 1;

    uint32_t rowOffA[4], rowOffB[2];
    #pragma unroll
    for (int mt = 0; mt < 4; mt++)
        rowOffA[mt] = (uint32_t)((warpM * 64 + mt * 16 + laneRowA) * 128);
    #pragma unroll
    for (int np = 0; np < 2; np++)
        rowOffB[np] = (uint32_t)((warpN * 32 + np * 16 + laneRowB) * 128) + 16384;

    float acc[4][4][4];
    #pragma unroll
    for (int mt = 0; mt < 4; mt++)
        #pragma unroll
        for (int nt = 0; nt < 4; nt++)
            #pragma unroll
            for (int j = 0; j < 4; j++) acc[mt][nt][j] = 0.f;

    for (int t = 0; t < KITERS; t++) {
        __syncthreads();   // buffer (t+2)%3 free (consumed in iter t-1)
        if (t + 2 < KITERS) {
            load_stage(sb, t + 2, tid, gA, gB);
            asm volatile("cp.async.commit_group;");
            asm volatile("cp.async.wait_group 2;" ::: "memory");
        } else {
            asm volatile("cp.async.wait_group 0;" ::: "memory");
        }
        __syncthreads();   // stage t visible

        const uint32_t sbase = sb + (t % STAGES) * STAGE_BYTES;
        #pragma unroll
        for (int ks = 0; ks < 4; ks++) {
            uint32_t a[4][4], b[2][4];
            const uint32_t xsA = (uint32_t)(((ks * 2 + kHalfA) ^ x7) << 4);
            #pragma unroll
            for (int mt = 0; mt < 4; mt++)
                ldsm4(a[mt], sbase + rowOffA[mt] + xsA);
            const uint32_t xsB = (uint32_t)(((ks * 2 + kHalfB) ^ x7) << 4);
            #pragma unroll
            for (int np = 0; np < 2; np++)
                ldsm4(b[np], sbase + rowOffB[np] + xsB);
            #pragma unroll
            for (int mt = 0; mt < 4; mt++)
                #pragma unroll
                for (int nt = 0; nt < 4; nt++)
                    mma16816(acc[mt][nt], a[mt], b[nt >> 1][(nt & 1) * 2],
                             b[nt >> 1][(nt & 1) * 2 + 1]);
        }
    }

    // ---- epilogue: masked sum-exp + gold capture ----
    #pragma unroll
    for (int mt = 0; mt < 4; mt++) {
        #pragma unroll
        for (int rh = 0; rh < 2; rh++) {
            int row = warpM * 64 + mt * 16 + rh * 8 + (lane >> 2);
            int labr = labsm[row];
            float se = 0.f;
            #pragma unroll
            for (int nt = 0; nt < 4; nt++) {
                int c0 = n0 + warpN * 32 + nt * 8 + (lane & 3) * 2;
                float v0 = acc[mt][nt][rh * 2 + 0];
                float v1 = acc[mt][nt][rh * 2 + 1];
                if (c0     < CCLS) se += __expf(v0);
                if (c0 + 1 < CCLS) se += __expf(v1);
                if (c0     == labr) g_gold[row0 + row] = v0;
                if (c0 + 1 == labr) g_gold[row0 + row] = v1;
            }
            se += __shfl_xor_sync(0xffffffffu, se, 1);
            se += __shfl_xor_sync(0xffffffffu, se, 2);
            if ((lane & 3) == 0) partial[row * 4 + warpN] = se;
        }
    }
    __syncthreads();
    if (tid < 128) {
        float t = partial[tid * 4] + partial[tid * 4 + 1]
                + partial[tid * 4 + 2] + partial[tid * 4 + 3];
        atomicAdd(&g_rowsum[row0 + tid], t);
    }
}

// ---------------------------------------------------------------------------
__global__ __launch_bounds__(256) void finalize(float* __restrict__ out) {
    int r = blockIdx.x * 256 + threadIdx.x;
    float loss = __logf(g_rowsum[r]) - g_gold[r];
    #pragma unroll
    for (int o = 16; o; o >>= 1) loss += __shfl_xor_sync(0xffffffffu, loss, o);
    __shared__ float ws[8];
    int w = threadIdx.x >> 5, l = threadIdx.x & 31;
    if (l == 0) ws[w] = loss;
    __syncthreads();
    if (threadIdx.x == 0) {
        float tot = 0.f;
        #pragma unroll
        for (int i = 0; i < 8; i++) tot += ws[i];
        atomicAdd(out, tot * (1.0f / (float)B_ROWS));
    }
}

// ---------------------------------------------------------------------------
extern "C" void kernel_launch(void* const* d_in, const int* in_sizes, int n_in,
                              void* d_out, int out_size) {
    const float*     hs = (const float*)d_in[0];
    const float*     pm = (const float*)d_in[1];
    const long long* lb = (const long long*)d_in[2];
    float* out = (float*)d_out;

    cudaFuncSetAttribute(gemm_ce, cudaFuncAttributeMaxDynamicSharedMemorySize, SMEM_TOTAL);

    zero_out<<<1, 1>>>(out);
    norm_kernel<<<B_ROWS, 256>>>(hs);
    convp<<<(1024 * DDIM) / 256, 256>>>(pm);
    dim3 grid(B_ROWS / BM, 8);
    gemm_ce<<<grid, 256, SMEM_TOTAL>>>(lb);
    finalize<<<B_ROWS / 256, 256>>>(out);
}

// round 8
// speedup vs baseline: 2.2816x; 1.0483x over previous
#include <cuda_runtime.h>
#include <cuda_bf16.h>
#include <cstdint>

#define B_ROWS 16384
#define DDIM   1024
#define CCLS   1000

#define BM 128
#define BN 128
#define BK 64
#define KITERS 16
#define STAGES 3
#define STAGE_BYTES 32768          // A 16KB + B 16KB
#define SM_MISC (STAGES * STAGE_BYTES)          // 98304
#define SMEM_TOTAL (SM_MISC + 128*4*4 + 128*4)  // + partial[128][4] + labsm[128]

// Scratch (allocation-free rule)
__device__ __nv_bfloat16 g_x[(size_t)B_ROWS * DDIM];
__device__ __nv_bfloat16 g_p[(size_t)1024 * DDIM];
__device__ float g_rowsum[B_ROWS];
__device__ float g_gold[B_ROWS];

__device__ __forceinline__ uint32_t smem_u32(const void* p) {
    uint32_t a;
    asm("{ .reg .u64 t; cvta.to.shared.u64 t, %1; cvt.u32.u64 %0, t; }" : "=r"(a) : "l"(p));
    return a;
}
__device__ __forceinline__ void cpa16(uint32_t daddr, const void* src) {
    asm volatile("cp.async.cg.shared.global [%0], [%1], 16;" :: "r"(daddr), "l"(src));
}
__device__ __forceinline__ void ldsm4(uint32_t* r, uint32_t addr) {
    asm volatile("ldmatrix.sync.aligned.m8n8.x4.shared.b16 {%0,%1,%2,%3}, [%4];"
                 : "=r"(r[0]), "=r"(r[1]), "=r"(r[2]), "=r"(r[3]) : "r"(addr));
}
__device__ __forceinline__ void mma16816(float* c, const uint32_t* a, uint32_t b0, uint32_t b1) {
    asm volatile(
        "mma.sync.aligned.m16n8k16.row.col.f32.bf16.bf16.f32 "
        "{%0,%1,%2,%3},{%4,%5,%6,%7},{%8,%9},{%0,%1,%2,%3};\n"
        : "+f"(c[0]), "+f"(c[1]), "+f"(c[2]), "+f"(c[3])
        : "r"(a[0]), "r"(a[1]), "r"(a[2]), "r"(a[3]), "r"(b0), "r"(b1));
}

// ---------------------------------------------------------------------------
__global__ void zero_out(float* out) { out[0] = 0.0f; }

// Fused prep: blocks [0, 16384) -> normalize rows of hs; [16384, 17408) -> convert P
__global__ __launch_bounds__(256) void prep_kernel(const float* __restrict__ hs,
                                                    const float* __restrict__ P) {
    if (blockIdx.x < B_ROWS) {
        int row = blockIdx.x;
        if (threadIdx.x == 0) g_rowsum[row] = 0.0f;
        const float4* src = (const float4*)(hs + (size_t)row * DDIM);
        float4 v = src[threadIdx.x];
        float ss = v.x * v.x + v.y * v.y + v.z * v.z + v.w * v.w;
        #pragma unroll
        for (int o = 16; o; o >>= 1) ss += __shfl_xor_sync(0xffffffffu, ss, o);
        __shared__ float wsum[8];
        int w = threadIdx.x >> 5, l = threadIdx.x & 31;
        if (l == 0) wsum[w] = ss;
        __syncthreads();
        float tot = 0.f;
        #pragma unroll
        for (int i = 0; i < 8; i++) tot += wsum[i];
        float s = rsqrtf(tot);
        __nv_bfloat162* dst = (__nv_bfloat162*)(g_x + (size_t)row * DDIM + threadIdx.x * 4);
        dst[0] = __floats2bfloat162_rn(v.x * s, v.y * s);
        dst[1] = __floats2bfloat162_rn(v.z * s, v.w * s);
    } else {
        int prow = blockIdx.x - B_ROWS;          // padded prototype row
        int col = threadIdx.x * 4;
        if (prow < CCLS) {
            const float4 v = *(const float4*)(P + (size_t)prow * DDIM + col);
            __nv_bfloat162* dst = (__nv_bfloat162*)(g_p + (size_t)prow * DDIM + col);
            dst[0] = __floats2bfloat162_rn(v.x, v.y);
            dst[1] = __floats2bfloat162_rn(v.z, v.w);
        } else {
            *(uint2*)(g_p + (size_t)prow * DDIM + col) = make_uint2(0u, 0u);
        }
    }
}

// ---------------------------------------------------------------------------
extern __shared__ char smem_g[];

__device__ __forceinline__ void load_stage(uint32_t base, int stage, int tid,
                                            const __nv_bfloat16* gA,
                                            const __nv_bfloat16* gB) {
    const int kk = stage * BK;
    #pragma unroll
    for (int i = 0; i < 4; i++) {
        int idx = tid + i * 256;
        int r = idx >> 3, s = idx & 7;
        uint32_t off = (uint32_t)(r * 128 + ((s ^ (r & 7)) << 4));
        cpa16(base + off,         gA + (size_t)r * DDIM + kk + s * 8);
        cpa16(base + 16384 + off, gB + (size_t)r * DDIM + kk + s * 8);
    }
}

__global__ __launch_bounds__(256, 2) void gemm_ce(const long long* __restrict__ labels) {
    uint32_t sb = smem_u32(smem_g);
    const int tid = threadIdx.x;
    const int wid = tid >> 5, lane = tid & 31;
    const int row0 = blockIdx.x * BM;
    const int n0   = blockIdx.y * BN;

    float* partial = (float*)(smem_g + SM_MISC);   // [128][4]
    int*   labsm   = (int*)(partial + 128 * 4);    // [128]

    const __nv_bfloat16* gA = g_x + (size_t)row0 * DDIM;
    const __nv_bfloat16* gB = g_p + (size_t)n0 * DDIM;

    load_stage(sb, 0, tid, gA, gB);
    asm volatile("cp.async.commit_group;");
    load_stage(sb + STAGE_BYTES, 1, tid, gA, gB);
    asm volatile("cp.async.commit_group;");
    if (tid < 128) labsm[tid] = (int)labels[row0 + tid];

    const int warpM = wid >> 2;      // 0..1  (64 rows each)
    const int warpN = wid & 3;       // 0..3  (32 cols each)
    const int x7 = lane & 7;
    const int laneRowA = (lane & 7) + ((lane >> 3) & 1) * 8;
    const int kHalfA   = lane >> 4;
    const int laneRowB = (lane & 7) + (lane >> 4) * 8;
    const int kHalfB   = (lane >> 3) & 1;

    uint32_t rowOffA[4], rowOffB[2];
    #pragma unroll
    for (int mt = 0; mt < 4; mt++)
        rowOffA[mt] = (uint32_t)((warpM * 64 + mt * 16 + laneRowA) * 128);
    #pragma unroll
    for (int np = 0; np < 2; np++)
        rowOffB[np] = (uint32_t)((warpN * 32 + np * 16 + laneRowB) * 128) + 16384;

    float acc[4][4][4];
    #pragma unroll
    for (int mt = 0; mt < 4; mt++)
        #pragma unroll
        for (int nt = 0; nt < 4; nt++)
            #pragma unroll
            for (int j = 0; j < 4; j++) acc[mt][nt][j] = 0.f;

    // rotating stage bases: cur = t%3, nxt = (t+2)%3
    uint32_t baseCur = sb;
    uint32_t baseNxt = sb + 2 * STAGE_BYTES;

    for (int t = 0; t < KITERS; t++) {
        if (t + 2 < KITERS) {
            asm volatile("cp.async.wait_group 1;" ::: "memory");
        } else {
            asm volatile("cp.async.wait_group 0;" ::: "memory");
        }
        __syncthreads();   // stage t visible to all; all warps done with stage t-1

        if (t + 2 < KITERS) {
            load_stage(baseNxt, t + 2, tid, gA, gB);
            asm volatile("cp.async.commit_group;");
        }

        const uint32_t sbase = baseCur;
        #pragma unroll
        for (int ks = 0; ks < 4; ks++) {
            uint32_t a[4][4], b[2][4];
            const uint32_t xsA = (uint32_t)(((ks * 2 + kHalfA) ^ x7) << 4);
            #pragma unroll
            for (int mt = 0; mt < 4; mt++)
                ldsm4(a[mt], sbase + rowOffA[mt] + xsA);
            const uint32_t xsB = (uint32_t)(((ks * 2 + kHalfB) ^ x7) << 4);
            #pragma unroll
            for (int np = 0; np < 2; np++)
                ldsm4(b[np], sbase + rowOffB[np] + xsB);
            #pragma unroll
            for (int mt = 0; mt < 4; mt++)
                #pragma unroll
                for (int nt = 0; nt < 4; nt++)
                    mma16816(acc[mt][nt], a[mt], b[nt >> 1][(nt & 1) * 2],
                             b[nt >> 1][(nt & 1) * 2 + 1]);
        }

        // rotate bases: cur advances, nxt advances (mod 3)
        uint32_t bc = baseCur + STAGE_BYTES;
        baseCur = (bc >= sb + 3 * STAGE_BYTES) ? sb : bc;
        uint32_t bn = baseNxt + STAGE_BYTES;
        baseNxt = (bn >= sb + 3 * STAGE_BYTES) ? sb : bn;
    }

    // ---- epilogue: masked sum-exp + gold capture ----
    #pragma unroll
    for (int mt = 0; mt < 4; mt++) {
        #pragma unroll
        for (int rh = 0; rh < 2; rh++) {
            int row = warpM * 64 + mt * 16 + rh * 8 + (lane >> 2);
            int labr = labsm[row];
            float se = 0.f;
            #pragma unroll
            for (int nt = 0; nt < 4; nt++) {
                int c0 = n0 + warpN * 32 + nt * 8 + (lane & 3) * 2;
                float v0 = acc[mt][nt][rh * 2 + 0];
                float v1 = acc[mt][nt][rh * 2 + 1];
                if (c0     < CCLS) se += __expf(v0);
                if (c0 + 1 < CCLS) se += __expf(v1);
                if (c0     == labr) g_gold[row0 + row] = v0;
                if (c0 + 1 == labr) g_gold[row0 + row] = v1;
            }
            se += __shfl_xor_sync(0xffffffffu, se, 1);
            se += __shfl_xor_sync(0xffffffffu, se, 2);
            if ((lane & 3) == 0) partial[row * 4 + warpN] = se;
        }
    }
    __syncthreads();
    if (tid < 128) {
        float t = partial[tid * 4] + partial[tid * 4 + 1]
                + partial[tid * 4 + 2] + partial[tid * 4 + 3];
        atomicAdd(&g_rowsum[row0 + tid], t);
    }
}

// ---------------------------------------------------------------------------
__global__ __launch_bounds__(256) void finalize(float* __restrict__ out) {
    int r = blockIdx.x * 256 + threadIdx.x;
    float loss = __logf(g_rowsum[r]) - g_gold[r];
    #pragma unroll
    for (int o = 16; o; o >>= 1) loss += __shfl_xor_sync(0xffffffffu, loss, o);
    __shared__ float ws[8];
    int w = threadIdx.x >> 5, l = threadIdx.x & 31;
    if (l == 0) ws[w] = loss;
    __syncthreads();
    if (threadIdx.x == 0) {
        float tot = 0.f;
        #pragma unroll
        for (int i = 0; i < 8; i++) tot += ws[i];
        atomicAdd(out, tot * (1.0f / (float)B_ROWS));
    }
}

// ---------------------------------------------------------------------------
extern "C" void kernel_launch(void* const* d_in, const int* in_sizes, int n_in,
                              void* d_out, int out_size) {
    const float*     hs = (const float*)d_in[0];
    const float*     pm = (const float*)d_in[1];
    const long long* lb = (const long long*)d_in[2];
    float* out = (float*)d_out;

    cudaFuncSetAttribute(gemm_ce, cudaFuncAttributeMaxDynamicSharedMemorySize, SMEM_TOTAL);

    zero_out<<<1, 1>>>(out);
    prep_kernel<<<B_ROWS + 1024, 256>>>(hs, pm);
    dim3 grid(B_ROWS / BM, 8);
    gemm_ce<<<grid, 256, SMEM_TOTAL>>>(lb);
    finalize<<<B_ROWS / 256, 256>>>(out);
}